// round 15
// baseline (speedup 1.0000x reference)
#include <cuda_runtime.h>
#include <cstddef>

// Shapes (fixed by the problem)
//  x_f:    (128, 256, 31, 31) f32
//  z_f:    (128, 256, 7, 7)   f32
//  heat_w: (1, 256, 3, 3), heat_b: (1,)
//  reg_w:  (4, 256, 3, 3), reg_b:  (4,)
//  out = concat(pred_heat (128,1,23,23), pred_reg (128,4,23,23)) f32

#define NB 128
#define NC 256
#define HEAT_ELEMS (NB * 529)          // 67712
#define OUT_ELEMS  (NB * 5 * 529)      // 338560

typedef unsigned long long ull;

// Packed f32x2 FMA (two independent exact fp32 FMAs in one instruction).
__device__ __forceinline__ ull fma2(ull a, ull b, ull c) {
    ull d;
    asm("fma.rn.f32x2 %0, %1, %2, %3;" : "=l"(d) : "l"(a), "l"(b), "l"(c));
    return d;
}

// smem layout, all channel-PAIR-packed float2 (identical to R14):
//  sx2: 4 pairs x 31 rows x 34 f2
//  sz2: 4 pairs x 7 rows x 8 f2      (row padded -> 16B-aligned z loads)
//  sc2: 4 x 25 x 26 f2               (even stride -> 16B-aligned LDS.128)
//  sw2: 4 pairs x 5 o x 10 taps f2   (padded -> 16B-aligned weight loads)
#define SX_F   (4 * 31 * 34 * 2)       // 8432 floats
#define SZ_F   (4 * 7 * 8 * 2)         // 448
#define SC_F   (4 * 25 * 26 * 2)       // 5200
#define SW_F   (4 * 5 * 10 * 2)        // 400
#define SMEM_FLOATS (SX_F + SZ_F + SC_F + SW_F)   // 14480 -> 57920 B

// ---------------------------------------------------------------------------
// K1 (fused): depthwise xcorr + both 3x3 head convs, channel-pair f32x2.
// Grid: 128*32 CTAs; CTA = (n, block of 8 channels). 256 threads, occ 3.
// == R14 exactly, except:
//  - Phase-C leftover units 256..275 spread across warps (was: all warp 0)
//  - biases folded into the c0==0 CTA's atomics (out pre-zeroed by memset)
// ---------------------------------------------------------------------------
__global__ __launch_bounds__(256, 3)
void fused_kernel(const float* __restrict__ x_f, const float* __restrict__ z_f,
                  const float* __restrict__ heat_w, const float* __restrict__ reg_w,
                  const float* __restrict__ heat_b, const float* __restrict__ reg_b,
                  float* __restrict__ out)
{
    extern __shared__ __align__(16) float sm[];
    float* sxf = sm;
    float* szf = sxf + SX_F;
    float* scf = szf + SZ_F;
    float* swf = scf + SC_F;

    ull* sx2 = reinterpret_cast<ull*>(sxf);
    ull* sz2 = reinterpret_cast<ull*>(szf);
    ull* sc2 = reinterpret_cast<ull*>(scf);
    ull* sw2 = reinterpret_cast<ull*>(swf);

    const int b   = blockIdx.x;
    const int n   = b >> 5;
    const int c0  = (b & 31) * 8;
    const int tid = threadIdx.x;

    // --- Phase A: staging into pair-interleaved layouts (R14 form) ---
    // x: 3844 channel-pair elements (m = pc*961 + q). Two 8-deep front-batched
    // load waves (MLP=16 LDG.32 in flight), then conflict-free STS.64 pairs.
    {
        const float* xg = x_f + ((size_t)n * NC + c0) * 961;
        #pragma unroll
        for (int hb = 0; hb < 2; hb++) {
            float ve[8], vo[8];
            #pragma unroll
            for (int kk = 0; kk < 8; kk++) {
                const int m = tid + (hb * 8 + kk) * 256;
                if (m < 3844) {
                    const int pc = m / 961;
                    const int q  = m - pc * 961;
                    const float* cb = xg + (size_t)(2 * pc) * 961 + q;
                    ve[kk] = cb[0];
                    vo[kk] = cb[961];
                }
            }
            #pragma unroll
            for (int kk = 0; kk < 8; kk++) {
                const int m = tid + (hb * 8 + kk) * 256;
                if (m < 3844) {
                    const int pc = m / 961;
                    const int q  = m - pc * 961;
                    const int r  = q / 31;
                    const int c  = q - r * 31;
                    float2 t; t.x = ve[kk]; t.y = vo[kk];
                    *reinterpret_cast<float2*>(sxf + (pc * 1054 + r * 34 + c) * 2) = t;
                }
            }
        }
    }
    // z: 392 floats, 2-deep front-batched.
    {
        const float* zg = z_f + ((size_t)n * NC + c0) * 49;
        float zv0 = zg[tid < 392 ? tid : 0];
        float zv1 = (tid + 256 < 392) ? zg[tid + 256] : 0.0f;
        #pragma unroll
        for (int k = 0; k < 2; k++) {
            int i = tid + k * 256;
            if (i >= 392) break;
            float val = k ? zv1 : zv0;
            int ch = i / 49;
            int t  = i - ch * 49;
            int u  = t / 7;
            int vv = t - u * 7;
            szf[((ch >> 1) * 56 + u * 8 + vv) * 2 + (ch & 1)] = val;
        }
    }
    // weights: pair-interleaved, (p,o) stride padded to 10 f2; pad slots = 0.
    for (int i = tid; i < SW_F / 2; i += 256) {     // (pair, o, tap 0..9)
        int p   = i / 50;
        int rr  = i - p * 50;
        int o   = rr / 10;
        int tap = rr - o * 10;
        float v0 = 0.0f, v1 = 0.0f;
        if (tap < 9) {
            int ch_e = c0 + 2 * p, ch_o = ch_e + 1;
            v0 = (o == 0) ? heat_w[ch_e * 9 + tap]
                          : reg_w[(((o - 1) * NC) + ch_e) * 9 + tap];
            v1 = (o == 0) ? heat_w[ch_o * 9 + tap]
                          : reg_w[(((o - 1) * NC) + ch_o) * 9 + tap];
        }
        swf[((p * 5 + o) * 10 + tap) * 2 + 0] = v0;
        swf[((p * 5 + o) * 10 + tap) * 2 + 1] = v1;
    }
    __syncthreads();

    // --- Phase B: depthwise xcorr, 13-col half-row of a channel PAIR ---
    if (tid < 200) {
        const int p    = tid / 50;           // channel pair 0..3
        const int rem  = tid - p * 50;
        const int y    = rem >> 1;           // corr row 0..24
        const int half = rem & 1;
        const int x0   = half ? 13 : 0;      // cols x0..x0+12 (13th dropped h1)

        ull acc[13];
        #pragma unroll
        for (int j = 0; j < 13; j++) acc[j] = 0ull;

        const ull* xb = sx2 + p * (31 * 34) + x0;
        const ull* zb = sz2 + p * 56;

        #pragma unroll
        for (int u = 0; u < 7; u++) {
            const ull* xrow = xb + (y + u) * 34;
            ull xr[19];
            #pragma unroll
            for (int k = 0; k < 19; k++) xr[k] = xrow[k];

            const ull* zrp = zb + u * 8;                 // 16B aligned
            ulonglong2 z01 = *reinterpret_cast<const ulonglong2*>(zrp);
            ulonglong2 z23 = *reinterpret_cast<const ulonglong2*>(zrp + 2);
            ulonglong2 z45 = *reinterpret_cast<const ulonglong2*>(zrp + 4);
            ull zv[7] = {z01.x, z01.y, z23.x, z23.y, z45.x, z45.y, zrp[6]};

            #pragma unroll
            for (int v = 0; v < 7; v++) {
                #pragma unroll
                for (int j = 0; j < 13; j++)
                    acc[j] = fma2(zv[v], xr[v + j], acc[j]);
            }
        }

        ull* crow = sc2 + p * 650 + y * 26 + x0;
        if (half == 0) {
            // crow 16B aligned: 6 x STS.128 + STS.64 for j 0..12.
            #pragma unroll
            for (int j = 0; j < 12; j += 2) {
                ulonglong2 t; t.x = acc[j]; t.y = acc[j + 1];
                *reinterpret_cast<ulonglong2*>(crow + j) = t;
            }
            crow[12] = acc[12];
        } else {
            // x0=13 (odd): scalar head, 5 x STS.128, scalar tail; j 0..11.
            crow[0] = acc[0];
            #pragma unroll
            for (int j = 1; j < 11; j += 2) {
                ulonglong2 t; t.x = acc[j]; t.y = acc[j + 1];
                *reinterpret_cast<ulonglong2*>(crow + j) = t;
            }
            crow[11] = acc[11];
        }
    }
    __syncthreads();

    // --- Phase C: partial 3x3 convs, 2-pixel units ---
    // 276 units = 23 rows x 12 column-pairs. Pass 0: unit == tid (<256).
    // Pass 1: units 256..275 on threads 0,12,24,...,228 (spread over warps).
    float* outh = out + (size_t)n * 529;
    float* outr = out + HEAT_ELEMS + (size_t)n * 4 * 529;

    // Biases: only the c0==0 CTA contributes them (out is pre-zeroed).
    float bias[5];
    {
        const float hb = (c0 == 0) ? heat_b[0] : 0.0f;
        bias[0] = hb;
        #pragma unroll
        for (int o = 0; o < 4; o++)
            bias[1 + o] = (c0 == 0) ? reg_b[o] : 0.0f;
    }

    int unit = tid;
    #pragma unroll 1
    for (int pass = 0; pass < 2; pass++) {
        if (pass == 1) {
            int q = tid / 12;
            if ((tid - q * 12) != 0 || q >= 20) break;
            unit = 256 + q;
        }

        const int y  = unit / 12;
        const int x0 = (unit - y * 12) * 2;

        ull a0[5], a1[5];
        #pragma unroll
        for (int o = 0; o < 5; o++) { a0[o] = 0ull; a1[o] = 0ull; }

        #pragma unroll
        for (int p = 0; p < 4; p++) {
            const ull* cb = sc2 + p * 650 + y * 26 + x0;   // even -> 16B align
            ull win[3][4];
            #pragma unroll
            for (int dy = 0; dy < 3; dy++) {
                ulonglong2 t0 = *reinterpret_cast<const ulonglong2*>(cb + dy * 26);
                ulonglong2 t1 = *reinterpret_cast<const ulonglong2*>(cb + dy * 26 + 2);
                win[dy][0] = t0.x; win[dy][1] = t0.y;
                win[dy][2] = t1.x; win[dy][3] = t1.y;
            }
            #pragma unroll
            for (int o = 0; o < 5; o++) {
                const ull* wp = sw2 + (p * 5 + o) * 10;    // 16B aligned
                ulonglong2 wA = *reinterpret_cast<const ulonglong2*>(wp);
                ulonglong2 wB = *reinterpret_cast<const ulonglong2*>(wp + 2);
                ulonglong2 wC = *reinterpret_cast<const ulonglong2*>(wp + 4);
                ulonglong2 wD = *reinterpret_cast<const ulonglong2*>(wp + 6);
                ull w[9] = {wA.x, wA.y, wB.x, wB.y,
                            wC.x, wC.y, wD.x, wD.y, wp[8]};
                #pragma unroll
                for (int dy = 0; dy < 3; dy++)
                    #pragma unroll
                    for (int dx = 0; dx < 3; dx++) {
                        const ull wv = w[dy * 3 + dx];
                        a0[o] = fma2(wv, win[dy][dx],     a0[o]);
                        a1[o] = fma2(wv, win[dy][dx + 1], a1[o]);
                    }
            }
        }

        const int sp = y * 23 + x0;
        {
            float2 f = *reinterpret_cast<float2*>(&a0[0]);
            atomicAdd(&outh[sp], f.x + f.y + bias[0]);
        }
        #pragma unroll
        for (int o = 0; o < 4; o++) {
            float2 f = *reinterpret_cast<float2*>(&a0[1 + o]);
            atomicAdd(&outr[o * 529 + sp], f.x + f.y + bias[1 + o]);
        }
        if (x0 < 22) {                        // 2nd pixel valid unless x0==22
            float2 fh = *reinterpret_cast<float2*>(&a1[0]);
            atomicAdd(&outh[sp + 1], fh.x + fh.y + bias[0]);
            #pragma unroll
            for (int o = 0; o < 4; o++) {
                float2 f = *reinterpret_cast<float2*>(&a1[1 + o]);
                atomicAdd(&outr[o * 529 + sp + 1], f.x + f.y + bias[1 + o]);
            }
        }
    }
}

// ---------------------------------------------------------------------------
extern "C" void kernel_launch(void* const* d_in, const int* in_sizes, int n_in,
                              void* d_out, int out_size)
{
    const float *x_f = nullptr, *z_f = nullptr, *heat_w = nullptr,
                *heat_b = nullptr, *reg_w = nullptr, *reg_b = nullptr;
    for (int i = 0; i < n_in; i++) {
        switch (in_sizes[i]) {
            case 128 * 256 * 31 * 31: x_f    = (const float*)d_in[i]; break;
            case 128 * 256 * 7 * 7:   z_f    = (const float*)d_in[i]; break;
            case 1 * 256 * 3 * 3:     heat_w = (const float*)d_in[i]; break;
            case 1:                   heat_b = (const float*)d_in[i]; break;
            case 4 * 256 * 3 * 3:     reg_w  = (const float*)d_in[i]; break;
            case 4:                   reg_b  = (const float*)d_in[i]; break;
            default: break;
        }
    }
    float* out = (float*)d_out;

    const int smem1 = SMEM_FLOATS * (int)sizeof(float);   // 57920 B
    cudaFuncSetAttribute(fused_kernel,
                         cudaFuncAttributeMaxDynamicSharedMemorySize, smem1);

    // Zero out (atomic partial sums accumulate on top; biases folded into
    // the c0==0 CTA's contribution). Async memset is graph-capturable.
    cudaMemsetAsync(out, 0, (size_t)out_size * sizeof(float), 0);
    fused_kernel<<<NB * 32, 256, smem1>>>(x_f, z_f, heat_w, reg_w,
                                          heat_b, reg_b, out);
}

// round 17
// speedup vs baseline: 1.2439x; 1.2439x over previous
#include <cuda_runtime.h>
#include <cstddef>

// Shapes (fixed by the problem)
//  x_f:    (128, 256, 31, 31) f32
//  z_f:    (128, 256, 7, 7)   f32
//  heat_w: (1, 256, 3, 3), heat_b: (1,)
//  reg_w:  (4, 256, 3, 3), reg_b:  (4,)
//  out = concat(pred_heat (128,1,23,23), pred_reg (128,4,23,23)) f32

#define NB 128
#define NC 256
#define HEAT_ELEMS (NB * 529)          // 67712
#define OUT_ELEMS  (NB * 5 * 529)      // 338560

typedef unsigned long long ull;

// Packed f32x2 FMA (two independent exact fp32 FMAs in one instruction).
__device__ __forceinline__ ull fma2(ull a, ull b, ull c) {
    ull d;
    asm("fma.rn.f32x2 %0, %1, %2, %3;" : "=l"(d) : "l"(a), "l"(b), "l"(c));
    return d;
}

// smem layout, all channel-PAIR-packed float2 (identical to R14 / 108.3us):
//  sx2: 4 pairs x 31 rows x 34 f2
//  sz2: 4 pairs x 7 rows x 8 f2      (row padded -> 16B-aligned z loads)
//  sc2: 4 x 25 x 26 f2               (even stride -> 16B-aligned LDS.128)
//  sw2: 4 pairs x 5 o x 10 taps f2   (padded -> 16B-aligned weight loads)
#define SX_F   (4 * 31 * 34 * 2)       // 8432 floats
#define SZ_F   (4 * 7 * 8 * 2)         // 448
#define SC_F   (4 * 25 * 26 * 2)       // 5200
#define SW_F   (4 * 5 * 10 * 2)        // 400
#define SMEM_FLOATS (SX_F + SZ_F + SC_F + SW_F)   // 14480 -> 57920 B

// ---------------------------------------------------------------------------
// K0: write biases into out (out is poisoned to 0xAA by the harness).
// float4 stores: 84640 vec4 stores instead of 338560 scalar (331 CTAs).
// 529 is odd, so output-channel id is computed per element within the vec4.
// ---------------------------------------------------------------------------
__global__ void init_out_kernel(const float* __restrict__ heat_b,
                                const float* __restrict__ reg_b,
                                float* __restrict__ out)
{
    int i4 = blockIdx.x * 256 + threadIdx.x;
    if (i4 >= OUT_ELEMS / 4) return;
    float4 v;
    if (i4 < HEAT_ELEMS / 4) {
        float hb = heat_b[0];
        v.x = hb; v.y = hb; v.z = hb; v.w = hb;
    } else {
        int j = i4 * 4 - HEAT_ELEMS;
        float t[4];
        #pragma unroll
        for (int k = 0; k < 4; k++) t[k] = reg_b[((j + k) / 529) & 3];
        v.x = t[0]; v.y = t[1]; v.z = t[2]; v.w = t[3];
    }
    reinterpret_cast<float4*>(out)[i4] = v;
}

// ---------------------------------------------------------------------------
// K1 (fused): depthwise xcorr + both 3x3 head convs, channel-pair f32x2.
// Grid: 128*32 CTAs; CTA = (n, block of 8 channels). 256 threads, occ 3.
// == R14 byte-for-byte (measured best, 108.3us). All structural variants
//    (tail-spread, bias-fold, retiles, occ-4, ring buffers) measured worse.
// ---------------------------------------------------------------------------
__global__ __launch_bounds__(256, 3)
void fused_kernel(const float* __restrict__ x_f, const float* __restrict__ z_f,
                  const float* __restrict__ heat_w, const float* __restrict__ reg_w,
                  float* __restrict__ out)
{
    extern __shared__ __align__(16) float sm[];
    float* sxf = sm;
    float* szf = sxf + SX_F;
    float* scf = szf + SZ_F;
    float* swf = scf + SC_F;

    ull* sx2 = reinterpret_cast<ull*>(sxf);
    ull* sz2 = reinterpret_cast<ull*>(szf);
    ull* sc2 = reinterpret_cast<ull*>(scf);
    ull* sw2 = reinterpret_cast<ull*>(swf);

    const int b   = blockIdx.x;
    const int n   = b >> 5;
    const int c0  = (b & 31) * 8;
    const int tid = threadIdx.x;

    // --- Phase A: staging into pair-interleaved layouts ---
    // x: 3844 channel-pair elements (m = pc*961 + q). Two 8-deep front-batched
    // load waves (MLP=16 LDG.32 in flight), then conflict-free STS.64 pairs.
    {
        const float* xg = x_f + ((size_t)n * NC + c0) * 961;
        #pragma unroll
        for (int hb = 0; hb < 2; hb++) {
            float ve[8], vo[8];
            #pragma unroll
            for (int kk = 0; kk < 8; kk++) {
                const int m = tid + (hb * 8 + kk) * 256;
                if (m < 3844) {
                    const int pc = m / 961;
                    const int q  = m - pc * 961;
                    const float* cb = xg + (size_t)(2 * pc) * 961 + q;
                    ve[kk] = cb[0];
                    vo[kk] = cb[961];
                }
            }
            #pragma unroll
            for (int kk = 0; kk < 8; kk++) {
                const int m = tid + (hb * 8 + kk) * 256;
                if (m < 3844) {
                    const int pc = m / 961;
                    const int q  = m - pc * 961;
                    const int r  = q / 31;
                    const int c  = q - r * 31;
                    float2 t; t.x = ve[kk]; t.y = vo[kk];
                    *reinterpret_cast<float2*>(sxf + (pc * 1054 + r * 34 + c) * 2) = t;
                }
            }
        }
    }
    // z: 392 floats, 2-deep front-batched.
    {
        const float* zg = z_f + ((size_t)n * NC + c0) * 49;
        float zv0 = zg[tid < 392 ? tid : 0];
        float zv1 = (tid + 256 < 392) ? zg[tid + 256] : 0.0f;
        #pragma unroll
        for (int k = 0; k < 2; k++) {
            int i = tid + k * 256;
            if (i >= 392) break;
            float val = k ? zv1 : zv0;
            int ch = i / 49;
            int t  = i - ch * 49;
            int u  = t / 7;
            int vv = t - u * 7;
            szf[((ch >> 1) * 56 + u * 8 + vv) * 2 + (ch & 1)] = val;
        }
    }
    // weights: pair-interleaved, (p,o) stride padded to 10 f2; pad slots = 0.
    for (int i = tid; i < SW_F / 2; i += 256) {     // (pair, o, tap 0..9)
        int p   = i / 50;
        int rr  = i - p * 50;
        int o   = rr / 10;
        int tap = rr - o * 10;
        float v0 = 0.0f, v1 = 0.0f;
        if (tap < 9) {
            int ch_e = c0 + 2 * p, ch_o = ch_e + 1;
            v0 = (o == 0) ? heat_w[ch_e * 9 + tap]
                          : reg_w[(((o - 1) * NC) + ch_e) * 9 + tap];
            v1 = (o == 0) ? heat_w[ch_o * 9 + tap]
                          : reg_w[(((o - 1) * NC) + ch_o) * 9 + tap];
        }
        swf[((p * 5 + o) * 10 + tap) * 2 + 0] = v0;
        swf[((p * 5 + o) * 10 + tap) * 2 + 1] = v1;
    }
    __syncthreads();

    // --- Phase B: depthwise xcorr, 13-col half-row of a channel PAIR ---
    if (tid < 200) {
        const int p    = tid / 50;           // channel pair 0..3
        const int rem  = tid - p * 50;
        const int y    = rem >> 1;           // corr row 0..24
        const int half = rem & 1;
        const int x0   = half ? 13 : 0;      // cols x0..x0+12 (13th dropped h1)

        ull acc[13];
        #pragma unroll
        for (int j = 0; j < 13; j++) acc[j] = 0ull;

        const ull* xb = sx2 + p * (31 * 34) + x0;
        const ull* zb = sz2 + p * 56;

        #pragma unroll
        for (int u = 0; u < 7; u++) {
            const ull* xrow = xb + (y + u) * 34;
            ull xr[19];
            #pragma unroll
            for (int k = 0; k < 19; k++) xr[k] = xrow[k];

            const ull* zrp = zb + u * 8;                 // 16B aligned
            ulonglong2 z01 = *reinterpret_cast<const ulonglong2*>(zrp);
            ulonglong2 z23 = *reinterpret_cast<const ulonglong2*>(zrp + 2);
            ulonglong2 z45 = *reinterpret_cast<const ulonglong2*>(zrp + 4);
            ull zv[7] = {z01.x, z01.y, z23.x, z23.y, z45.x, z45.y, zrp[6]};

            #pragma unroll
            for (int v = 0; v < 7; v++) {
                #pragma unroll
                for (int j = 0; j < 13; j++)
                    acc[j] = fma2(zv[v], xr[v + j], acc[j]);
            }
        }

        ull* crow = sc2 + p * 650 + y * 26 + x0;
        if (half == 0) {
            // crow 16B aligned: 6 x STS.128 + STS.64 for j 0..12.
            #pragma unroll
            for (int j = 0; j < 12; j += 2) {
                ulonglong2 t; t.x = acc[j]; t.y = acc[j + 1];
                *reinterpret_cast<ulonglong2*>(crow + j) = t;
            }
            crow[12] = acc[12];
        } else {
            // x0=13 (odd): scalar head, 5 x STS.128, scalar tail; j 0..11.
            crow[0] = acc[0];
            #pragma unroll
            for (int j = 1; j < 11; j += 2) {
                ulonglong2 t; t.x = acc[j]; t.y = acc[j + 1];
                *reinterpret_cast<ulonglong2*>(crow + j) = t;
            }
            crow[11] = acc[11];
        }
    }
    __syncthreads();

    // --- Phase C: partial 3x3 convs, 2-pixel units ---
    // 276 units = 23 rows x 12 column-pairs; unit owns pixels (y,x0),(y,x0+1).
    float* outh = out + (size_t)n * 529;
    float* outr = out + HEAT_ELEMS + (size_t)n * 4 * 529;

    for (int unit = tid; unit < 276; unit += 256) {
        const int y  = unit / 12;
        const int x0 = (unit - y * 12) * 2;

        ull a0[5], a1[5];
        #pragma unroll
        for (int o = 0; o < 5; o++) { a0[o] = 0ull; a1[o] = 0ull; }

        #pragma unroll
        for (int p = 0; p < 4; p++) {
            const ull* cb = sc2 + p * 650 + y * 26 + x0;   // even -> 16B align
            ull win[3][4];
            #pragma unroll
            for (int dy = 0; dy < 3; dy++) {
                ulonglong2 t0 = *reinterpret_cast<const ulonglong2*>(cb + dy * 26);
                ulonglong2 t1 = *reinterpret_cast<const ulonglong2*>(cb + dy * 26 + 2);
                win[dy][0] = t0.x; win[dy][1] = t0.y;
                win[dy][2] = t1.x; win[dy][3] = t1.y;
            }
            #pragma unroll
            for (int o = 0; o < 5; o++) {
                const ull* wp = sw2 + (p * 5 + o) * 10;    // 16B aligned
                ulonglong2 wA = *reinterpret_cast<const ulonglong2*>(wp);
                ulonglong2 wB = *reinterpret_cast<const ulonglong2*>(wp + 2);
                ulonglong2 wC = *reinterpret_cast<const ulonglong2*>(wp + 4);
                ulonglong2 wD = *reinterpret_cast<const ulonglong2*>(wp + 6);
                ull w[9] = {wA.x, wA.y, wB.x, wB.y,
                            wC.x, wC.y, wD.x, wD.y, wp[8]};
                #pragma unroll
                for (int dy = 0; dy < 3; dy++)
                    #pragma unroll
                    for (int dx = 0; dx < 3; dx++) {
                        const ull wv = w[dy * 3 + dx];
                        a0[o] = fma2(wv, win[dy][dx],     a0[o]);
                        a1[o] = fma2(wv, win[dy][dx + 1], a1[o]);
                    }
            }
        }

        const int sp = y * 23 + x0;
        {
            float2 f = *reinterpret_cast<float2*>(&a0[0]);
            atomicAdd(&outh[sp], f.x + f.y);
        }
        #pragma unroll
        for (int o = 0; o < 4; o++) {
            float2 f = *reinterpret_cast<float2*>(&a0[1 + o]);
            atomicAdd(&outr[o * 529 + sp], f.x + f.y);
        }
        if (x0 < 22) {                        // 2nd pixel valid unless x0==22
            float2 fh = *reinterpret_cast<float2*>(&a1[0]);
            atomicAdd(&outh[sp + 1], fh.x + fh.y);
            #pragma unroll
            for (int o = 0; o < 4; o++) {
                float2 f = *reinterpret_cast<float2*>(&a1[1 + o]);
                atomicAdd(&outr[o * 529 + sp + 1], f.x + f.y);
            }
        }
    }
}

// ---------------------------------------------------------------------------
extern "C" void kernel_launch(void* const* d_in, const int* in_sizes, int n_in,
                              void* d_out, int out_size)
{
    const float *x_f = nullptr, *z_f = nullptr, *heat_w = nullptr,
                *heat_b = nullptr, *reg_w = nullptr, *reg_b = nullptr;
    for (int i = 0; i < n_in; i++) {
        switch (in_sizes[i]) {
            case 128 * 256 * 31 * 31: x_f    = (const float*)d_in[i]; break;
            case 128 * 256 * 7 * 7:   z_f    = (const float*)d_in[i]; break;
            case 1 * 256 * 3 * 3:     heat_w = (const float*)d_in[i]; break;
            case 1:                   heat_b = (const float*)d_in[i]; break;
            case 4 * 256 * 3 * 3:     reg_w  = (const float*)d_in[i]; break;
            case 4:                   reg_b  = (const float*)d_in[i]; break;
            default: break;
        }
    }
    float* out = (float*)d_out;

    const int smem1 = SMEM_FLOATS * (int)sizeof(float);   // 57920 B
    cudaFuncSetAttribute(fused_kernel,
                         cudaFuncAttributeMaxDynamicSharedMemorySize, smem1);

    init_out_kernel<<<(OUT_ELEMS / 4 + 255) / 256, 256>>>(heat_b, reg_b, out);
    fused_kernel<<<NB * 32, 256, smem1>>>(x_f, z_f, heat_w, reg_w, out);
}